// round 3
// baseline (speedup 1.0000x reference)
#include <cuda_runtime.h>
#include <cuda_bf16.h>
#include <math_constants.h>

// Problem constants
#define NPTS 8192
#define KCOMP 64
#define JBLOCKS 32          // 32 blocks x 256 threads = 8192 j's
#define ISPLITS 16          // i dimension split into 16 chunks of 512
#define ICHUNK 512

// KDE constants (bw = 0.5*128/8192 = 2^-7 exactly)
// -0.5/bw^2 = -8192 exactly; prescale by log2(e) so a single EX2 suffices.
#define LOG2E 1.4426950408889634
__device__ __constant__ float CKDE = (float)(-8192.0 * LOG2E);            // exp2 arg scale
__device__ __constant__ float NORM = (float)(1.0 / (2.5066282746310002 * 0.0078125 * 8192.0)); // 1/(sqrt(2*pi)*bw*N)

// Scratch (device globals — no allocations allowed)
__device__ float g_coef[KCOMP];              // w_k / sqrt(2*pi*var_k)
__device__ float g_a[KCOMP];                 // -0.5*log2e / var_k   (exp2-prescaled)
__device__ float g_partial[ISPLITS][NPTS];   // deterministic partial KDE sums
__device__ float g_block_sums[JBLOCKS];

// Single-MUFU exp2 (flushes large-negative args to 0, matching fp32 underflow)
__device__ __forceinline__ float ex2(float x) {
    float r;
    asm("ex2.approx.ftz.f32 %0, %1;" : "=f"(r) : "f"(x));
    return r;
}

// ---------------------------------------------------------------------------
// 1) Softmax + per-component constants
// ---------------------------------------------------------------------------
__global__ void gmm_prep(const float* __restrict__ wl, const float* __restrict__ lv) {
    __shared__ float sl[KCOMP], se[KCOMP];
    int k = threadIdx.x;
    sl[k] = wl[k];
    __syncthreads();
    float m = -CUDART_INF_F;
    #pragma unroll
    for (int i = 0; i < KCOMP; i++) m = fmaxf(m, sl[i]);
    float e = __expf(sl[k] - m);
    se[k] = e;
    __syncthreads();
    float s = 0.0f;
    #pragma unroll
    for (int i = 0; i < KCOMP; i++) s += se[i];
    float w = e / s;
    float var = __expf(lv[k]);
    g_coef[k] = w * rsqrtf(6.283185307179586f * var);
    g_a[k]    = (float)(-0.5 * LOG2E) / var;
}

// ---------------------------------------------------------------------------
// 2) Pairwise KDE partial sums. block = (j-block, i-split). 512 blocks total.
//    MUFU-bound: 1 EX2 per pair, 67.1M pairs.
// ---------------------------------------------------------------------------
__global__ __launch_bounds__(256) void gmm_kde(const float* __restrict__ x) {
    __shared__ float sx[ICHUNK];
    int t = threadIdx.x;
    int j = blockIdx.x * 256 + t;
    int i0 = blockIdx.y * ICHUNK;

    sx[t]       = x[i0 + t];
    sx[t + 256] = x[i0 + t + 256];
    __syncthreads();

    float xj = x[j];
    float ck = CKDE;
    float acc = 0.0f;
    #pragma unroll 8
    for (int ii = 0; ii < ICHUNK; ii++) {
        float d = xj - sx[ii];
        acc += ex2(d * d * ck);
    }
    g_partial[blockIdx.y][j] = acc;
}

// ---------------------------------------------------------------------------
// 3) Mixture pdf per j, combine with KDE, squared diff, block reduce
// ---------------------------------------------------------------------------
__global__ __launch_bounds__(256) void gmm_finalize(const float* __restrict__ x,
                                                    const float* __restrict__ means) {
    __shared__ float sm[KCOMP], sc[KCOMP], sa[KCOMP];
    __shared__ float rs[256];
    int t = threadIdx.x;
    if (t < KCOMP) {
        sm[t] = means[t];
        sc[t] = g_coef[t];
        sa[t] = g_a[t];
    }
    __syncthreads();

    int j = blockIdx.x * 256 + t;
    float xj = x[j];

    float mix = 0.0f;
    #pragma unroll
    for (int k = 0; k < KCOMP; k++) {
        float d = xj - sm[k];
        mix += sc[k] * ex2(d * d * sa[k]);
    }

    float s = 0.0f;
    #pragma unroll
    for (int p = 0; p < ISPLITS; p++) s += g_partial[p][j];
    float data = s * NORM;

    float diff = mix - data;
    float sq = diff * diff;

    rs[t] = sq;
    __syncthreads();
    #pragma unroll
    for (int off = 128; off > 0; off >>= 1) {
        if (t < off) rs[t] += rs[t + off];
        __syncthreads();
    }
    if (t == 0) g_block_sums[blockIdx.x] = rs[0];
}

// ---------------------------------------------------------------------------
// 4) Final 32-way reduction into d_out
// ---------------------------------------------------------------------------
__global__ void gmm_reduce32(float* __restrict__ out) {
    float v = g_block_sums[threadIdx.x];
    #pragma unroll
    for (int o = 16; o > 0; o >>= 1) v += __shfl_down_sync(0xffffffffu, v, o);
    if (threadIdx.x == 0) out[0] = v;
}

extern "C" void kernel_launch(void* const* d_in, const int* in_sizes, int n_in,
                              void* d_out, int out_size) {
    const float* x  = (const float*)d_in[0];  // [8192]
    const float* wl = (const float*)d_in[1];  // [64] weight_logits
    const float* mu = (const float*)d_in[2];  // [64] means
    const float* lv = (const float*)d_in[3];  // [64] log_vars
    float* out = (float*)d_out;

    gmm_prep<<<1, KCOMP>>>(wl, lv);
    gmm_kde<<<dim3(JBLOCKS, ISPLITS), 256>>>(x);
    gmm_finalize<<<JBLOCKS, 256>>>(x, mu);
    gmm_reduce32<<<1, 32>>>(out);
}

// round 4
// speedup vs baseline: 1.1951x; 1.1951x over previous
#include <cuda_runtime.h>
#include <cuda_bf16.h>
#include <math_constants.h>

// Problem constants
#define NPTS   8192
#define KCOMP  64
#define NBMAX  127          // max bins (hist array size)
#define MAINBLOCKS 256
#define JPB    32           // sorted j's per main block
#define TILE   2048         // candidate staging tile (floats)

// KDE: bw = 0.5*128/8192 = 2^-7 exactly  ->  exp(-8192*d^2) = exp2(C*d^2)
#define LOG2E 1.4426950408889634
__device__ __constant__ float CKDE = (float)(-8192.0 * LOG2E);
__device__ __constant__ float NORM = (float)(1.0 / (2.5066282746310002 * 0.0078125 * 8192.0));
// ex2.ftz flushes to 0 for arg < -126  ->  |d| > 0.10327. Window radius with margin:
#define RCUT 0.104f

// Scratch (device globals — no allocation allowed)
__device__ float g_xs[NPTS];              // x values, counting-sorted by bin
__device__ int   g_binstart[NBMAX + 2];   // bin start offsets (exclusive scan), [nb] = NPTS
__device__ int   g_nb;
__device__ float g_coef[KCOMP];           // w_k / sqrt(2*pi*var_k)
__device__ float g_a[KCOMP];              // -0.5*log2e / var_k
__device__ float g_block_sums[MAINBLOCKS];
__device__ int   g_ticket = 0;            // last-block ticket; self-resets each call

__device__ __forceinline__ float ex2(float x) {
    float r;
    asm("ex2.approx.ftz.f32 %0, %1;" : "=f"(r) : "f"(x));
    return r;
}

// ---------------------------------------------------------------------------
// 1) Prep: min/max, histogram, counting-sort scatter, softmax constants.
//    Single block, 1024 threads, 8 elements/thread.
// ---------------------------------------------------------------------------
__global__ __launch_bounds__(1024) void gmm_prep(const float* __restrict__ x,
                                                 const float* __restrict__ wl,
                                                 const float* __restrict__ lv) {
    __shared__ float red[1024];
    __shared__ int   h[NBMAX + 1];
    __shared__ int   bs[NBMAX + 2];
    __shared__ int   cur[NBMAX + 1];
    __shared__ float sl[KCOMP];
    __shared__ float s_mn, s_invW;
    __shared__ int   s_nb;

    int t = threadIdx.x;

    float xv[8];
    float mn = CUDART_INF_F, mx = -CUDART_INF_F;
    #pragma unroll
    for (int e = 0; e < 8; e++) {
        float v = x[t + e * 1024];
        xv[e] = v;
        mn = fminf(mn, v);
        mx = fmaxf(mx, v);
    }

    // block min
    red[t] = mn; __syncthreads();
    #pragma unroll
    for (int off = 512; off > 0; off >>= 1) {
        if (t < off) red[t] = fminf(red[t], red[t + off]);
        __syncthreads();
    }
    mn = red[0]; __syncthreads();
    // block max
    red[t] = mx; __syncthreads();
    #pragma unroll
    for (int off = 512; off > 0; off >>= 1) {
        if (t < off) red[t] = fmaxf(red[t], red[t + off]);
        __syncthreads();
    }
    mx = red[0];

    if (t == 0) {
        float range = mx - mn;
        int nb = (range > RCUT) ? (int)(range / RCUT) : 1;  // floor => W = range/nb >= RCUT
        nb = min(nb, NBMAX);
        if (nb < 1) nb = 1;
        s_nb = nb;
        s_mn = mn;
        s_invW = (range > 0.0f) ? (float)nb / range : 0.0f;
        g_nb = nb;
    }
    if (t <= NBMAX) h[t] = 0;
    if (t < KCOMP)  sl[t] = wl[t];
    __syncthreads();

    int   nb   = s_nb;
    float bmn  = s_mn;
    float invW = s_invW;

    int bidx[8];
    #pragma unroll
    for (int e = 0; e < 8; e++) {
        int b = (int)((xv[e] - bmn) * invW);
        b = min(b, nb - 1);
        b = max(b, 0);
        bidx[e] = b;
        atomicAdd(&h[b], 1);
    }
    __syncthreads();

    if (t == 0) {
        int acc = 0;
        for (int b = 0; b < nb; b++) { bs[b] = acc; acc += h[b]; }
        bs[nb] = acc;  // == NPTS
    }
    __syncthreads();

    if (t <= nb) g_binstart[t] = bs[t];
    if (t < nb)  cur[t] = bs[t];
    __syncthreads();

    #pragma unroll
    for (int e = 0; e < 8; e++) {
        int pos = atomicAdd(&cur[bidx[e]], 1);
        g_xs[pos] = xv[e];
    }

    // softmax + per-component constants (threads 0..63; sl synced above)
    if (t < KCOMP) {
        float m = -CUDART_INF_F;
        #pragma unroll
        for (int i = 0; i < KCOMP; i++) m = fmaxf(m, sl[i]);
        float ssum = 0.0f;
        #pragma unroll
        for (int i = 0; i < KCOMP; i++) ssum += __expf(sl[i] - m);
        float w   = __expf(sl[t] - m) / ssum;
        float var = __expf(lv[t]);
        g_coef[t] = w * rsqrtf(6.283185307179586f * var);
        g_a[t]    = (float)(-0.5 * LOG2E) / var;
    }
}

// ---------------------------------------------------------------------------
// 2) Main: windowed KDE over sorted array + mixture pdf + MSE reduction.
//    256 blocks x 256 threads; block handles 32 sorted j's; 8 warp-slices per j.
//    Each warp iterates a strided slice of the candidate window; candidates are
//    uniform per warp (broadcast LDS), lanes hold distinct j's.
// ---------------------------------------------------------------------------
__global__ __launch_bounds__(256) void gmm_main(const float* __restrict__ means,
                                                float* __restrict__ out) {
    __shared__ float st[TILE];
    __shared__ float sp[256];
    __shared__ int   sbs[NBMAX + 2];
    __shared__ float smn[KCOMP], scf[KCOMP], sa[KCOMP];
    __shared__ int   s_lastflag;

    int tid = threadIdx.x;
    int jj  = tid & 31;       // j within block (lane)
    int s   = tid >> 5;       // warp-slice 0..7
    int j0  = blockIdx.x * JPB;
    int nb  = g_nb;

    if (tid <= nb) sbs[tid] = g_binstart[tid];
    if (tid < KCOMP) {
        smn[tid] = means[tid];
        scf[tid] = g_coef[tid];
        sa[tid]  = g_a[tid];
    }
    __syncthreads();

    float xj = g_xs[j0 + jj];
    float ck = CKDE;

    // candidate window: bins of [j0, j0+31] +/- 1, contiguous in sorted order
    int j1 = j0 + JPB - 1;
    int bf = 0, bl = 0;
    for (int b = 1; b < nb; b++) {
        if (sbs[b] <= j0) bf = b;
        if (sbs[b] <= j1) bl = b;
    }
    int c0 = sbs[max(bf - 1, 0)];
    int c1 = sbs[min(bl + 2, nb)];

    float acc = 0.0f;
    for (int base = c0; base < c1; base += TILE) {
        int n = min(TILE, c1 - base);
        for (int i = tid; i < n; i += 256) st[i] = g_xs[base + i];
        __syncthreads();
        #pragma unroll 4
        for (int i = s; i < n; i += 8) {
            float d = xj - st[i];            // exact for close pairs (Sterbenz)
            acc += ex2(ck * d * d);
        }
        __syncthreads();
    }
    sp[tid] = acc;
    __syncthreads();

    if (s == 0) {
        float data = 0.0f;
        #pragma unroll
        for (int p = 0; p < 8; p++) data += sp[p * 32 + jj];
        data *= NORM;

        float mix = 0.0f;
        #pragma unroll
        for (int k = 0; k < KCOMP; k++) {
            float d = xj - smn[k];
            mix += scf[k] * ex2(sa[k] * d * d);
        }

        float diff = mix - data;
        float v = diff * diff;
        #pragma unroll
        for (int o = 16; o > 0; o >>= 1) v += __shfl_down_sync(0xffffffffu, v, o);
        if (jj == 0) g_block_sums[blockIdx.x] = v;
    }

    // last-block final reduction (deterministic tree; atomic only on int ticket)
    if (tid == 0) {
        __threadfence();
        int tk = atomicAdd(&g_ticket, 1);
        s_lastflag = (tk == (int)gridDim.x - 1);
    }
    __syncthreads();
    if (s_lastflag) {
        sp[tid] = g_block_sums[tid];
        __syncthreads();
        #pragma unroll
        for (int off = 128; off > 0; off >>= 1) {
            if (tid < off) sp[tid] += sp[tid + off];
            __syncthreads();
        }
        if (tid == 0) {
            out[0] = sp[0];
            g_ticket = 0;   // reset for next graph replay
        }
    }
}

extern "C" void kernel_launch(void* const* d_in, const int* in_sizes, int n_in,
                              void* d_out, int out_size) {
    const float* x  = (const float*)d_in[0];  // [8192]
    const float* wl = (const float*)d_in[1];  // [64] weight_logits
    const float* mu = (const float*)d_in[2];  // [64] means
    const float* lv = (const float*)d_in[3];  // [64] log_vars
    float* out = (float*)d_out;

    gmm_prep<<<1, 1024>>>(x, wl, lv);
    gmm_main<<<MAINBLOCKS, 256>>>(mu, out);
}

// round 6
// speedup vs baseline: 1.3448x; 1.1252x over previous
#include <cuda_runtime.h>
#include <cuda_bf16.h>
#include <math_constants.h>

// Problem constants
#define NPTS    8192
#define KCOMP   64
#define NB_MAX  256          // max bins
#define WPB     8            // warps (j's) per main block
#define MBLOCKS (NPTS / WPB) // 1024 main blocks

// KDE: bw = 0.5*128/8192 = 2^-7 exactly  ->  exp(-8192*d^2) = exp2(CKDE*d^2)
#define LOG2E 1.4426950408889634
__device__ __constant__ float CKDE = (float)(-8192.0 * LOG2E);
__device__ __constant__ float NORM = (float)(1.0 / (2.5066282746310002 * 0.0078125 * 8192.0));
// ex2.ftz flushes to 0 for arg < -126  ->  |d| > 0.10327. Radius with margin:
#define RCUT   0.104f
#define HALF_R 0.052f        // bin width >= RCUT/2; window [b-2, b+3) covers +/-RCUT

// Scratch (device globals — no allocation allowed)
__device__ float g_xs[NPTS];              // x counting-sorted by bin
__device__ int   g_binstart[NB_MAX + 1];  // exclusive-scan offsets; [nb..NB_MAX] = NPTS
__device__ int   g_nb;
__device__ float g_mn, g_invW;
__device__ float g_coef[KCOMP];           // w_k / sqrt(2*pi*var_k)
__device__ float g_a[KCOMP];              // -0.5*log2e / var_k
__device__ float g_block_sums[MBLOCKS];
__device__ int   g_ticket = 0;            // self-resets each call

__device__ __forceinline__ float ex2(float x) {
    float r;
    asm("ex2.approx.ftz.f32 %0, %1;" : "=f"(r) : "f"(x));
    return r;
}

// ---------------------------------------------------------------------------
// 1) Prep: min/max (shfl), histogram, warp-parallel scan, counting-sort
//    scatter, softmax constants. One block, 1024 threads, 8 elems/thread.
// ---------------------------------------------------------------------------
__global__ __launch_bounds__(1024) void gmm_prep(const float* __restrict__ x,
                                                 const float* __restrict__ wl,
                                                 const float* __restrict__ lv) {
    __shared__ float wmn[32], wmx[32];
    __shared__ int   h[NB_MAX];
    __shared__ int   bs[NB_MAX + 1];
    __shared__ int   cur[NB_MAX];
    __shared__ float s_mn, s_invW;
    __shared__ int   s_nb;

    int t = threadIdx.x, lane = t & 31, wid = t >> 5;

    float xv[8];
    float mn = CUDART_INF_F, mx = -CUDART_INF_F;
    #pragma unroll
    for (int e = 0; e < 8; e++) {
        float v = x[t + e * 1024];
        xv[e] = v;
        mn = fminf(mn, v);
        mx = fmaxf(mx, v);
    }
    #pragma unroll
    for (int o = 16; o > 0; o >>= 1) {
        mn = fminf(mn, __shfl_xor_sync(0xffffffffu, mn, o));
        mx = fmaxf(mx, __shfl_xor_sync(0xffffffffu, mx, o));
    }
    if (lane == 0) { wmn[wid] = mn; wmx[wid] = mx; }
    if (t < NB_MAX) h[t] = 0;
    __syncthreads();
    if (t < 32) {
        float a = wmn[t], b = wmx[t];
        #pragma unroll
        for (int o = 16; o > 0; o >>= 1) {
            a = fminf(a, __shfl_xor_sync(0xffffffffu, a, o));
            b = fmaxf(b, __shfl_xor_sync(0xffffffffu, b, o));
        }
        if (t == 0) {
            float range = b - a;
            int nb = (range > HALF_R) ? (int)(range / HALF_R) : 1; // floor => W >= R/2
            nb = min(nb, NB_MAX);
            if (nb < 1) nb = 1;
            float invW = (range > 0.0f) ? (float)nb / range : 0.0f;
            s_nb = nb; s_mn = a; s_invW = invW;
            g_nb = nb; g_mn = a; g_invW = invW;
        }
    }
    __syncthreads();

    int   nb   = s_nb;
    float bmn  = s_mn;
    float invW = s_invW;

    int bidx[8];
    #pragma unroll
    for (int e = 0; e < 8; e++) {
        int b = (int)((xv[e] - bmn) * invW);
        b = min(b, nb - 1);
        b = max(b, 0);
        bidx[e] = b;
        atomicAdd(&h[b], 1);
    }
    __syncthreads();

    // Warp 0 scans all 256 bins: 8 bins/lane serial + shfl inclusive scan.
    if (t < 32) {
        int v[8], p[8], run = 0;
        #pragma unroll
        for (int k = 0; k < 8; k++) {
            v[k] = h[t * 8 + k];
            p[k] = run;
            run += v[k];
        }
        int incl = run;
        #pragma unroll
        for (int o = 1; o < 32; o <<= 1) {
            int u = __shfl_up_sync(0xffffffffu, incl, o);
            if (lane >= o) incl += u;
        }
        int excl = incl - run;
        #pragma unroll
        for (int k = 0; k < 8; k++) bs[t * 8 + k] = excl + p[k];
        if (t == 31) bs[NB_MAX] = incl;   // == NPTS
    }
    __syncthreads();

    if (t <= NB_MAX) g_binstart[t] = bs[t];
    if (t < NB_MAX)  cur[t] = bs[t];
    __syncthreads();

    #pragma unroll
    for (int e = 0; e < 8; e++) {
        int pos = atomicAdd(&cur[bidx[e]], 1);
        g_xs[pos] = xv[e];
    }

    // softmax + per-component constants.
    // NOTE: reads wl[] directly from global (L1) — no shared staging, no
    // cross-warp race (the round-4 bug: __syncwarp doesn't sync warps 0 and 1).
    if (t < KCOMP) {
        float m = -CUDART_INF_F;
        #pragma unroll
        for (int i = 0; i < KCOMP; i++) m = fmaxf(m, __ldg(&wl[i]));
        float ssum = 0.0f;
        #pragma unroll
        for (int i = 0; i < KCOMP; i++) ssum += __expf(__ldg(&wl[i]) - m);
        float w   = __expf(__ldg(&wl[t]) - m) / ssum;
        float var = __expf(lv[t]);
        g_coef[t] = w * rsqrtf(6.283185307179586f * var);
        g_a[t]    = (float)(-0.5 * LOG2E) / var;
    }
}

// ---------------------------------------------------------------------------
// 2) Main: one warp per sorted j. Lanes stride the candidate window with
//    coalesced LDG (x is L1-resident). Mixture distributed 2 comps/lane.
//    1024 blocks x 256 threads -> fine-grained HW load balancing.
// ---------------------------------------------------------------------------
__global__ __launch_bounds__(256) void gmm_main(const float* __restrict__ means,
                                                float* __restrict__ out) {
    __shared__ float smn[KCOMP], scf[KCOMP], sa[KCOMP];
    __shared__ float wsum[WPB];
    __shared__ float rs[256];
    __shared__ int   s_last;

    int tid = threadIdx.x, lane = tid & 31, w = tid >> 5;
    if (tid < KCOMP) {
        smn[tid] = means[tid];
        scf[tid] = g_coef[tid];
        sa[tid]  = g_a[tid];
    }
    __syncthreads();

    int j = blockIdx.x * WPB + w;
    float xj = g_xs[j];                      // broadcast
    int nb = g_nb;
    int b = (int)((xj - g_mn) * g_invW);     // identical formula to prep => same bin
    b = min(b, nb - 1);
    b = max(b, 0);
    int c0 = g_binstart[max(b - 2, 0)];
    int c1 = g_binstart[min(b + 3, nb)];

    float ck = CKDE;
    float acc = 0.0f;
    #pragma unroll 4
    for (int i = c0 + lane; i < c1; i += 32) {
        float d = xj - g_xs[i];              // Sterbenz-exact for close pairs
        acc += ex2(ck * d * d);
    }

    // mixture pdf: 2 components per lane
    float d1 = xj - smn[lane];
    float mixp = scf[lane] * ex2(sa[lane] * d1 * d1);
    float d2 = xj - smn[lane + 32];
    mixp += scf[lane + 32] * ex2(sa[lane + 32] * d2 * d2);

    #pragma unroll
    for (int o = 16; o > 0; o >>= 1) {
        acc  += __shfl_xor_sync(0xffffffffu, acc, o);
        mixp += __shfl_xor_sync(0xffffffffu, mixp, o);
    }
    if (lane == 0) {
        float diff = mixp - acc * NORM;
        wsum[w] = diff * diff;
    }
    __syncthreads();

    if (tid == 0) {
        float v = 0.0f;
        #pragma unroll
        for (int p = 0; p < WPB; p++) v += wsum[p];
        g_block_sums[blockIdx.x] = v;
        __threadfence();
        int tk = atomicAdd(&g_ticket, 1);
        s_last = (tk == MBLOCKS - 1);
    }
    __syncthreads();

    if (s_last) {
        __threadfence();                     // acquire: order reads after ticket
        float v = 0.0f;
        #pragma unroll
        for (int q = 0; q < MBLOCKS / 256; q++) v += g_block_sums[tid + q * 256];
        rs[tid] = v;
        __syncthreads();
        #pragma unroll
        for (int off = 128; off > 0; off >>= 1) {
            if (tid < off) rs[tid] += rs[tid + off];
            __syncthreads();
        }
        if (tid == 0) {
            out[0] = rs[0];
            g_ticket = 0;   // reset for next graph replay
        }
    }
}

extern "C" void kernel_launch(void* const* d_in, const int* in_sizes, int n_in,
                              void* d_out, int out_size) {
    const float* x  = (const float*)d_in[0];  // [8192]
    const float* wl = (const float*)d_in[1];  // [64] weight_logits
    const float* mu = (const float*)d_in[2];  // [64] means
    const float* lv = (const float*)d_in[3];  // [64] log_vars
    float* out = (float*)d_out;

    gmm_prep<<<1, 1024>>>(x, wl, lv);
    gmm_main<<<MBLOCKS, 256>>>(mu, out);
}